// round 6
// baseline (speedup 1.0000x reference)
#include <cuda_runtime.h>
#include <float.h>
#include <math.h>

#define DIMC 320
#define NMAX 4096
#define SORTN 4096

// ---------------- scratch (static device allocations; no cudaMalloc) ----------------
__device__ float g_X0   [NMAX*DIMC];
__device__ float g_down0[NMAX*DIMC];
__device__ float g_down1[NMAX*DIMC];
__device__ float g_Xp   [NMAX*DIMC];
__device__ float g_Xb   [NMAX*DIMC];
__device__ float g_Xf   [NMAX*DIMC];
__device__ float g_G    [NMAX*DIMC];
__device__ float g_gate [NMAX*DIMC];
__device__ float g_Xu   [NMAX*DIMC];
__device__ float g_Hp   [NMAX];
__device__ float g_scores[NMAX];
__device__ float g_vals0[NMAX];
__device__ float g_vals1[NMAX];
__device__ int   g_idx0 [NMAX];
__device__ int   g_idx1 [NMAX];
__device__ int   g_inv  [NMAX];
__device__ unsigned g_bits[NMAX*(NMAX/32)];

// ---------------- adjacency bitmask ----------------
// No early return: every lane participates in the full-mask ballot.
__global__ void bits_kernel(const float* __restrict__ A, unsigned* __restrict__ bits, long total) {
    long t = (long)blockIdx.x * blockDim.x + threadIdx.x;
    bool nz = (t < total) && (A[t] != 0.0f);
    unsigned b = __ballot_sync(0xffffffffu, nz);
    if ((t & 31) == 0 && t < total) bits[t >> 5] = b;
}

// ---------------- generalized GEMM: C = act(A1@W1 [+ A2@W2] + bias [+bias2]) [+ res] ----
// A rows contiguous with ld=320 (K=320 per input). W row-major K x 320. N = 320.
// Templated on block-M so small-M launches still fill 148 SMs.
#define BN 64
#define BK 16
#define KT (DIMC / BK)   // 20 k-tiles per input

template<int BMT>
__global__ void __launch_bounds__(256)
gemm_kernel(int M,
            const float* __restrict__ A1, const float* __restrict__ W1,
            const float* __restrict__ A2, const float* __restrict__ W2,
            const float* __restrict__ bias, const float* __restrict__ bias2,
            const float* __restrict__ res, float* __restrict__ C, int act)
{
    constexpr int R = BMT / 16;     // rows per thread (8 or 4)
    constexpr int V = BMT / 64;     // float4 A-loads per thread (2 or 1)
    __shared__ float As[2][BK][BMT + 4];
    __shared__ float Ws[2][BK][BN];
    int tid = threadIdx.x;
    int m0 = blockIdx.x * BMT;
    int n0 = blockIdx.y * BN;
    int tm = tid >> 4;   // 0..15 -> rows tm*R..tm*R+R-1
    int tn = tid & 15;   // 0..15 -> cols tn*4..tn*4+3

    // W-tile load mapping
    int kw = tid >> 4;             // 0..15
    int nq = tid & 15;             // 0..15

    float acc[R][4];
#pragma unroll
    for (int i = 0; i < R; i++)
#pragma unroll
        for (int j = 0; j < 4; j++) acc[i][j] = 0.f;

    int nt = A2 ? 2 * KT : KT;

    float4 pa[V], pw;
    // prefetch tile 0
#pragma unroll
    for (int v = 0; v < V; v++) {
        int f = tid * V + v;            // 0..BMT*4-1
        int row = f >> 2;               // 0..BMT-1
        int kq = (f & 3) * 4;           // 0,4,8,12
        int gr = m0 + row;
        pa[v] = (gr < M) ? *(const float4*)(A1 + (long)gr * DIMC + kq)
                         : make_float4(0.f, 0.f, 0.f, 0.f);
    }
    pw = *(const float4*)(W1 + (long)kw * DIMC + n0 + nq * 4);
    // store tile 0 into buf 0
#pragma unroll
    for (int v = 0; v < V; v++) {
        int f = tid * V + v;
        int row = f >> 2;
        int kq = (f & 3) * 4;
        As[0][kq + 0][row] = pa[v].x; As[0][kq + 1][row] = pa[v].y;
        As[0][kq + 2][row] = pa[v].z; As[0][kq + 3][row] = pa[v].w;
    }
    *(float4*)&Ws[0][kw][nq * 4] = pw;
    __syncthreads();

    for (int t = 0; t < nt; t++) {
        int buf = t & 1;
        bool pf = (t + 1) < nt;
        if (pf) {
            int tn1 = t + 1;
            const float* Ai = (tn1 >= KT) ? A2 : A1;
            const float* Wi = (tn1 >= KT) ? W2 : W1;
            int kt = (tn1 >= KT) ? tn1 - KT : tn1;
#pragma unroll
            for (int v = 0; v < V; v++) {
                int f = tid * V + v;
                int row = f >> 2;
                int kq = (f & 3) * 4;
                int gr = m0 + row;
                pa[v] = (gr < M) ? *(const float4*)(Ai + (long)gr * DIMC + kt * BK + kq)
                                 : make_float4(0.f, 0.f, 0.f, 0.f);
            }
            pw = *(const float4*)(Wi + (long)(kt * BK + kw) * DIMC + n0 + nq * 4);
        }
#pragma unroll
        for (int k = 0; k < BK; k++) {
            float av[R];
#pragma unroll
            for (int ii = 0; ii < R / 4; ii++) {
                float4 a = *(const float4*)&As[buf][k][tm * R + ii * 4];
                av[ii * 4 + 0] = a.x; av[ii * 4 + 1] = a.y;
                av[ii * 4 + 2] = a.z; av[ii * 4 + 3] = a.w;
            }
            float4 b = *(const float4*)&Ws[buf][k][tn * 4];
            float bv[4] = {b.x, b.y, b.z, b.w};
#pragma unroll
            for (int i = 0; i < R; i++)
#pragma unroll
                for (int j = 0; j < 4; j++)
                    acc[i][j] += av[i] * bv[j];
        }
        if (pf) {
            int nb = buf ^ 1;
#pragma unroll
            for (int v = 0; v < V; v++) {
                int f = tid * V + v;
                int row = f >> 2;
                int kq = (f & 3) * 4;
                As[nb][kq + 0][row] = pa[v].x; As[nb][kq + 1][row] = pa[v].y;
                As[nb][kq + 2][row] = pa[v].z; As[nb][kq + 3][row] = pa[v].w;
            }
            *(float4*)&Ws[nb][kw][nq * 4] = pw;
        }
        __syncthreads();
    }

    // epilogue: vectorized (columns tn*4..tn*4+3 are contiguous, 16B aligned)
    float bv[4];
#pragma unroll
    for (int j = 0; j < 4; j++) {
        bv[j] = bias ? bias[n0 + tn * 4 + j] : 0.f;
        if (bias2) bv[j] += bias2[n0 + tn * 4 + j];
    }
#pragma unroll
    for (int i = 0; i < R; i++) {
        int gr = m0 + tm * R + i;
        if (gr < M) {
            float v[4];
#pragma unroll
            for (int j = 0; j < 4; j++) {
                v[j] = acc[i][j] + bv[j];
                if (act == 1) v[j] = fmaxf(v[j], 0.f);
                else if (act == 2) v[j] = 1.f / (1.f + expf(-v[j]));
            }
            if (res) {
                float4 rr = *(const float4*)(res + (long)gr * DIMC + n0 + tn * 4);
                v[0] += rr.x; v[1] += rr.y; v[2] += rr.z; v[3] += rr.w;
            }
            float4 o; o.x = v[0]; o.y = v[1]; o.z = v[2]; o.w = v[3];
            *(float4*)(C + (long)gr * DIMC + n0 + tn * 4) = o;
        }
    }
}

// ---------------- Hp = X @ pW + (pwb + pb) ----------------
__global__ void hp_kernel(int M, const float* __restrict__ X, const float* __restrict__ pW,
                          const float* __restrict__ pwb, const float* __restrict__ pb,
                          float* __restrict__ Hp)
{
    int r = blockIdx.x * 4 + (threadIdx.x >> 5);
    int lane = threadIdx.x & 31;
    if (r >= M) return;
    float s = 0.f;
#pragma unroll
    for (int k = lane; k < DIMC; k += 32) s += X[(long)r * DIMC + k] * pW[k];
#pragma unroll
    for (int o = 16; o > 0; o >>= 1) s += __shfl_down_sync(0xffffffffu, s, o);
    if (lane == 0) Hp[r] = s + pwb[0] + pb[0];
}

// ---------------- masked softmax scores ----------------
// valid(r,c) = (c==r) || A_orig[orow, ocol] != 0, via bitmask; phi1*h1[r] cancels in softmax.
// Pass 1 gathers idxmap/h1 once and caches masked operands in shared; pass 2 reads shared only.
__global__ void attn_kernel(int n, const float* __restrict__ h1,
                            const unsigned* __restrict__ bits,
                            const int* __restrict__ idxmap,
                            const float* __restrict__ phi_i,
                            float* __restrict__ scores)
{
    __shared__ unsigned sb[128];
    __shared__ float red[128];
    __shared__ float red2[128];
    __shared__ float mv [SORTN];   // valid ? phi0*h1[c] : -FLT_MAX
    __shared__ float hvs[SORTN];   // h1[c]
    int r = blockIdx.x;
    int tid = threadIdx.x;   // 128 threads
    float phi0 = phi_i[0];
    int orow = idxmap ? idxmap[r] : r;
    sb[tid] = bits[(long)orow * 128 + tid];
    __syncthreads();

    float m = -FLT_MAX;
    for (int c = tid; c < n; c += 128) {
        int oc = idxmap ? idxmap[c] : c;
        bool valid = (c == r) || ((sb[oc >> 5] >> (oc & 31)) & 1u);
        float hv = h1[c];
        float x = valid ? phi0 * hv : -FLT_MAX;
        mv[c] = x;
        hvs[c] = hv;
        m = fmaxf(m, x);
    }
    red[tid] = m; __syncthreads();
    for (int o = 64; o > 0; o >>= 1) {
        if (tid < o) red[tid] = fmaxf(red[tid], red[tid + o]);
        __syncthreads();
    }
    m = red[0];
    __syncthreads();

    float se = 0.f, sh = 0.f;
    for (int c = tid; c < n; c += 128) {
        float x = mv[c];
        if (x > -FLT_MAX) {
            float e = expf(x - m);
            se += e; sh += e * hvs[c];
        }
    }
    red[tid] = se; red2[tid] = sh; __syncthreads();
    for (int o = 64; o > 0; o >>= 1) {
        if (tid < o) { red[tid] += red[tid + o]; red2[tid] += red2[tid + o]; }
        __syncthreads();
    }
    if (tid == 0) {
        float x = (red2[0] / red[0]) * 0.01f;
        scores[r] = 1.f / (1.f + expf(-x));
    }
}

// ---------------- top-k via single-block bitonic sort (desc value, asc index on ties) ----
__global__ void __launch_bounds__(1024)
topk_kernel(int n, int kk, const float* __restrict__ scores,
            int* __restrict__ idx_out, float* __restrict__ vals_out)
{
    __shared__ float sv[SORTN];
    __shared__ int   si[SORTN];
    int tid = threadIdx.x;
    for (int i = tid; i < SORTN; i += 1024) {
        if (i < n) { sv[i] = scores[i]; si[i] = i; }
        else       { sv[i] = -FLT_MAX;  si[i] = 0x7FFFFFFF; }
    }
    __syncthreads();
    for (int k = 2; k <= SORTN; k <<= 1) {
        for (int j = k >> 1; j > 0; j >>= 1) {
            for (int i = tid; i < SORTN; i += 1024) {
                int ixj = i ^ j;
                if (ixj > i) {
                    float vi = sv[i], vj = sv[ixj];
                    int ii = si[i], ij = si[ixj];
                    bool g = (vi > vj) || (vi == vj && ii < ij);  // i correctly before ixj (descending)
                    bool descBlock = ((i & k) == 0);
                    if (descBlock ? !g : g) {
                        sv[i] = vj; sv[ixj] = vi;
                        si[i] = ij; si[ixj] = ii;
                    }
                }
            }
            __syncthreads();
        }
    }
    for (int i = tid; i < kk; i += 1024) {
        idx_out[i] = si[i];
        vals_out[i] = sv[i];
    }
}

// ---------------- pooling / scatter glue ----------------
__global__ void pool_kernel(const int* __restrict__ idx, const float* __restrict__ vals,
                            const float* __restrict__ Xin, float* __restrict__ Xout)
{
    int r = blockIdx.x;
    float v = vals[r];
    long src = idx[r];
    for (int d = threadIdx.x; d < DIMC; d += blockDim.x)
        Xout[(long)r * DIMC + d] = Xin[src * DIMC + d] * v;
}

__global__ void seti_kernel(int n, int* __restrict__ p, int v) {
    int i = blockIdx.x * blockDim.x + threadIdx.x;
    if (i < n) p[i] = v;
}

__global__ void invset_kernel(int kk, const int* __restrict__ idx, int* __restrict__ inv) {
    int i = blockIdx.x * blockDim.x + threadIdx.x;
    if (i < kk) inv[idx[i]] = i;
}

__global__ void scatter_kernel(const int* __restrict__ inv, const float* __restrict__ Xin,
                               float* __restrict__ Xf)
{
    int r = blockIdx.x;
    int s = inv[r];
    for (int d = threadIdx.x; d < DIMC; d += blockDim.x)
        Xf[(long)r * DIMC + d] = (s >= 0) ? Xin[(long)s * DIMC + d] : 0.f;
}

__global__ void copy_kernel(long n, const float* __restrict__ src, float* __restrict__ dst) {
    long i = (long)blockIdx.x * blockDim.x + threadIdx.x;
    if (i < n) dst[i] = src[i];
}

// ---------------- host orchestration ----------------
static inline void run_gemm(int M, const float* A1, const float* W1,
                            const float* A2, const float* W2,
                            const float* bias, const float* bias2,
                            const float* res, float* C, int act)
{
    if (M > 2048) {
        dim3 grid((M + 127) / 128, DIMC / BN);
        gemm_kernel<128><<<grid, 256>>>(M, A1, W1, A2, W2, bias, bias2, res, C, act);
    } else {
        dim3 grid((M + 63) / 64, DIMC / BN);
        gemm_kernel<64><<<grid, 256>>>(M, A1, W1, A2, W2, bias, bias2, res, C, act);
    }
}

extern "C" void kernel_launch(void* const* d_in, const int* in_sizes, int n_in,
                              void* d_out, int out_size)
{
    const float* A    = (const float*)d_in[0];
    const float* X    = (const float*)d_in[1];
    const float* W0   = (const float*)d_in[2];
    const float* b0   = (const float*)d_in[3];
    const float* Wb   = (const float*)d_in[4];
    const float* bb   = (const float*)d_in[5];
    const float* We   = (const float*)d_in[6];
    const float* be   = (const float*)d_in[7];
    const float* dW   = (const float*)d_in[8];
    const float* db   = (const float*)d_in[9];
    const float* uW   = (const float*)d_in[10];
    const float* ub   = (const float*)d_in[11];
    const float* pW   = (const float*)d_in[12];
    const float* pwb  = (const float*)d_in[13];
    const float* pb   = (const float*)d_in[14];
    const float* phi  = (const float*)d_in[15];
    const float* agWg = (const float*)d_in[16];
    const float* agbg = (const float*)d_in[17];
    const float* agWs = (const float*)d_in[18];
    const float* agbs = (const float*)d_in[19];
    const float* agWp = (const float*)d_in[20];
    const float* agbp = (const float*)d_in[21];

    int n0 = in_sizes[1] / DIMC;                 // 4096
    int kk0 = (int)(0.8 * (double)n0);           // 3276 (matches Python int(0.8*n))
    int kk1 = (int)(0.6 * (double)kk0);          // 1965

    float *pX0, *pD0, *pD1, *pXp, *pXb, *pXf, *pG, *pGate, *pXu, *pHp, *pSc, *pV0, *pV1;
    int *pI0, *pI1, *pInv;
    unsigned* pBits;
    cudaGetSymbolAddress((void**)&pX0,  g_X0);
    cudaGetSymbolAddress((void**)&pD0,  g_down0);
    cudaGetSymbolAddress((void**)&pD1,  g_down1);
    cudaGetSymbolAddress((void**)&pXp,  g_Xp);
    cudaGetSymbolAddress((void**)&pXb,  g_Xb);
    cudaGetSymbolAddress((void**)&pXf,  g_Xf);
    cudaGetSymbolAddress((void**)&pG,   g_G);
    cudaGetSymbolAddress((void**)&pGate,g_gate);
    cudaGetSymbolAddress((void**)&pXu,  g_Xu);
    cudaGetSymbolAddress((void**)&pHp,  g_Hp);
    cudaGetSymbolAddress((void**)&pSc,  g_scores);
    cudaGetSymbolAddress((void**)&pV0,  g_vals0);
    cudaGetSymbolAddress((void**)&pV1,  g_vals1);
    cudaGetSymbolAddress((void**)&pI0,  g_idx0);
    cudaGetSymbolAddress((void**)&pI1,  g_idx1);
    cudaGetSymbolAddress((void**)&pInv, g_inv);
    cudaGetSymbolAddress((void**)&pBits,g_bits);

    const long DD = (long)DIMC * DIMC;

    // adjacency bitmask
    long totalA = (long)n0 * n0;
    bits_kernel<<<(unsigned)((totalA + 255) / 256), 256>>>(A, pBits, totalA);

    // X0 = relu(X @ W0 + b0)   (= "start")
    run_gemm(n0, X, W0, nullptr, nullptr, b0, nullptr, nullptr, pX0, 1);

    // ---- level 0 down ----
    run_gemm(n0, pX0, dW, nullptr, nullptr, db, nullptr, nullptr, pD0, 1);
    hp_kernel<<<(n0 + 3) / 4, 128>>>(n0, pD0, pW, pwb, pb, pHp);
    attn_kernel<<<n0, 128>>>(n0, pHp, pBits, nullptr, phi, pSc);
    topk_kernel<<<1, 1024>>>(n0, kk0, pSc, pI0, pV0);
    pool_kernel<<<kk0, 128>>>(pI0, pV0, pD0, pXp);

    // ---- level 1 down ----
    run_gemm(kk0, pXp, dW + DD, nullptr, nullptr, db + DIMC, nullptr, nullptr, pD1, 1);
    hp_kernel<<<(kk0 + 3) / 4, 128>>>(kk0, pD1, pW + DIMC, pwb + 1, pb + 1, pHp);
    attn_kernel<<<kk0, 128>>>(kk0, pHp, pBits, pI0, phi + 2, pSc);
    topk_kernel<<<1, 1024>>>(kk0, kk1, pSc, pI1, pV1);
    pool_kernel<<<kk1, 128>>>(pI1, pV1, pD1, pXp);

    // ---- bottleneck ----
    run_gemm(kk1, pXp, Wb, nullptr, nullptr, bb, nullptr, nullptr, pXb, 1);

    // ---- unpool i=0 (u=1, n=kk0) ----
    seti_kernel<<<(kk0 + 255) / 256, 256>>>(kk0, pInv, -1);
    invset_kernel<<<(kk1 + 255) / 256, 256>>>(kk1, pI1, pInv);
    scatter_kernel<<<kk0, 128>>>(pInv, pXb, pXf);
    run_gemm(kk0, pXf, agWg, pD1, agWs, agbg, agbs, nullptr, pG, 1);
    run_gemm(kk0, pG, agWp, nullptr, nullptr, agbp, nullptr, nullptr, pGate, 2);
    run_gemm(kk0, pXf, uW, pGate, uW + DD, ub, nullptr, pD1, pXu, 1);

    // ---- unpool i=1 (u=0, n=n0) ----
    seti_kernel<<<(n0 + 255) / 256, 256>>>(n0, pInv, -1);
    invset_kernel<<<(kk0 + 255) / 256, 256>>>(kk0, pI0, pInv);
    scatter_kernel<<<n0, 128>>>(pInv, pXu, pXf);
    run_gemm(n0, pXf, agWg + DD, pD0, agWs + DD, agbg + DIMC, agbs + DIMC, nullptr, pG, 1);
    run_gemm(n0, pG, agWp + DD, nullptr, nullptr, agbp + DIMC, nullptr, nullptr, pGate, 2);
    run_gemm(n0, pXf, uW + 2 * DD, pGate, uW + 2 * DD + DD, ub + DIMC, nullptr, pD0, pXu, 1);

    // ---- output head: out = relu([Xu, start] @ We + be) ----
    run_gemm(n0, pXu, We, pX0, We + DD, be, nullptr, nullptr, (float*)d_out, 1);

    // second tuple element: start
    long sz = (long)n0 * DIMC;
    if (out_size >= 2 * sz)
        copy_kernel<<<(unsigned)((sz + 255) / 256), 256>>>(sz, pX0, (float*)d_out + sz);
}